// round 3
// baseline (speedup 1.0000x reference)
#include <cuda_runtime.h>
#include <cstdint>

#define EPS 1e-5f
#define NBATCH 16
#define GROUPS 4
#define BPG 4                           // batches per group (4 x 16MB = 64MB << 126MB L2)
#define PER (4 * 1024 * 1024)           // elements per batch (C*H*W)
#define PER4 (PER / 4)                  // float4s per batch = 1,048,576

#define RED_THREADS 256
#define RED_BLOCKS 256                  // blocks per batch
#define RED_STRIDE (RED_BLOCKS * RED_THREADS)   // 65536
#define RED_ITERS (PER4 / RED_STRIDE)           // 16
#define RED_UNROLL 8

#define NORM_THREADS 256
#define NORM_F4_PER_THREAD 8
#define NORM_F4_PER_BLOCK (NORM_THREADS * NORM_F4_PER_THREAD)   // 2048
#define NORM_BLOCKS (PER4 / NORM_F4_PER_BLOCK)                  // 512 per batch

// Scratch (allocation-free requirement -> __device__ globals)
__device__ float        g_psum[NBATCH * RED_BLOCKS];
__device__ float        g_psumsq[NBATCH * RED_BLOCKS];
__device__ unsigned int g_pcnt[NBATCH * RED_BLOCKS];
__device__ float        g_mean[NBATCH];
__device__ float        g_inv[NBATCH];
__device__ unsigned int g_cnt[NBATCH];   // zero-init; reset by last block each use

// ---------------------------------------------------------------------------
// Pass 1 (per group): per-batch partial reduction of (sum, sumsq, nnz count),
// with finalize fused via the threadfence-reduction last-block pattern.
// Masked entries are exactly 0.0f so sum/sumsq over ALL elements equal the
// masked sums -> branch-free hot loop.
// ---------------------------------------------------------------------------
__global__ __launch_bounds__(RED_THREADS)
void reduce_finalize_kernel(const float4* __restrict__ x, int group) {
    const int b = group * BPG + blockIdx.y;
    const float4* xb = x + (size_t)b * PER4;

    float s = 0.f, ss = 0.f;
    unsigned int c = 0;

    const int base = blockIdx.x * RED_THREADS + threadIdx.x;

    #pragma unroll 1
    for (int j = 0; j < RED_ITERS; j += RED_UNROLL) {
        float4 v[RED_UNROLL];
        #pragma unroll
        for (int k = 0; k < RED_UNROLL; k++)
            v[k] = xb[base + (size_t)(j + k) * RED_STRIDE];
        #pragma unroll
        for (int k = 0; k < RED_UNROLL; k++) {
            s  += v[k].x + v[k].y + v[k].z + v[k].w;
            ss  = fmaf(v[k].x, v[k].x, ss);
            ss  = fmaf(v[k].y, v[k].y, ss);
            ss  = fmaf(v[k].z, v[k].z, ss);
            ss  = fmaf(v[k].w, v[k].w, ss);
            c  += (v[k].x != 0.f) + (v[k].y != 0.f) + (v[k].z != 0.f) + (v[k].w != 0.f);
        }
    }

    // block reduce
    #pragma unroll
    for (int off = 16; off > 0; off >>= 1) {
        s  += __shfl_xor_sync(0xFFFFFFFFu, s,  off);
        ss += __shfl_xor_sync(0xFFFFFFFFu, ss, off);
        c  += __shfl_xor_sync(0xFFFFFFFFu, c,  off);
    }

    __shared__ float sh_s[RED_THREADS / 32];
    __shared__ float sh_ss[RED_THREADS / 32];
    __shared__ unsigned int sh_c[RED_THREADS / 32];
    const int lane = threadIdx.x & 31;
    const int warp = threadIdx.x >> 5;
    if (lane == 0) { sh_s[warp] = s; sh_ss[warp] = ss; sh_c[warp] = c; }
    __syncthreads();

    if (warp == 0) {
        s  = (lane < RED_THREADS / 32) ? sh_s[lane]  : 0.f;
        ss = (lane < RED_THREADS / 32) ? sh_ss[lane] : 0.f;
        c  = (lane < RED_THREADS / 32) ? sh_c[lane]  : 0u;
        #pragma unroll
        for (int off = 4; off > 0; off >>= 1) {
            s  += __shfl_xor_sync(0xFFFFFFFFu, s,  off);
            ss += __shfl_xor_sync(0xFFFFFFFFu, ss, off);
            c  += __shfl_xor_sync(0xFFFFFFFFu, c,  off);
        }
        if (lane == 0) {
            const int idx = b * RED_BLOCKS + blockIdx.x;
            g_psum[idx]   = s;
            g_psumsq[idx] = ss;
            g_pcnt[idx]   = c;
        }
    }

    // ---- last-block-per-batch finalize ----
    __shared__ unsigned int is_last;
    __threadfence();
    if (threadIdx.x == 0)
        is_last = (atomicAdd(&g_cnt[b], 1u) == RED_BLOCKS - 1u);
    __syncthreads();

    if (is_last) {
        __threadfence();   // acquire: make all blocks' partials visible
        const int t = threadIdx.x;
        double ds  = (double)g_psum[b * RED_BLOCKS + t];
        double dss = (double)g_psumsq[b * RED_BLOCKS + t];
        unsigned long long dc = g_pcnt[b * RED_BLOCKS + t];

        #pragma unroll
        for (int off = 16; off > 0; off >>= 1) {
            ds  += __shfl_xor_sync(0xFFFFFFFFu, ds,  off);
            dss += __shfl_xor_sync(0xFFFFFFFFu, dss, off);
            dc  += __shfl_xor_sync(0xFFFFFFFFu, dc,  off);
        }
        __shared__ double fs[RED_THREADS / 32];
        __shared__ double fss[RED_THREADS / 32];
        __shared__ unsigned long long fc[RED_THREADS / 32];
        if (lane == 0) { fs[warp] = ds; fss[warp] = dss; fc[warp] = dc; }
        __syncthreads();
        if (threadIdx.x == 0) {
            double S = 0.0, SS = 0.0; unsigned long long C = 0;
            #pragma unroll
            for (int w = 0; w < RED_THREADS / 32; w++) { S += fs[w]; SS += fss[w]; C += fc[w]; }
            const double n    = (double)C;
            const double mean = S / n;
            const double var  = (SS - S * S / n) / (n - 1.0);   // m2 term analytically 0
            g_mean[b] = (float)mean;
            g_inv[b]  = (float)(1.0 / (sqrt(var) + (double)EPS));
            g_cnt[b]  = 0;          // reset for next graph replay
        }
    }
}

// ---------------------------------------------------------------------------
// Pass 2 (per group): elementwise normalize. x for this group is L2-resident
// from the reduce pass; streaming stores keep the output from evicting it.
// ---------------------------------------------------------------------------
__global__ __launch_bounds__(NORM_THREADS)
void normalize_kernel(const float4* __restrict__ x, float4* __restrict__ out, int group) {
    const int b = group * BPG + blockIdx.y;
    const size_t off = (size_t)b * PER4 + (size_t)blockIdx.x * NORM_F4_PER_BLOCK + threadIdx.x;

    const float mean = g_mean[b];
    const float inv  = g_inv[b];

    float4 v[NORM_F4_PER_THREAD];
    #pragma unroll
    for (int k = 0; k < NORM_F4_PER_THREAD; k++)
        v[k] = x[off + (size_t)k * NORM_THREADS];

    #pragma unroll
    for (int k = 0; k < NORM_F4_PER_THREAD; k++) {
        float4 o;
        o.x = (v[k].x != 0.f) ? (v[k].x - mean) * inv : 0.f;
        o.y = (v[k].y != 0.f) ? (v[k].y - mean) * inv : 0.f;
        o.z = (v[k].z != 0.f) ? (v[k].z - mean) * inv : 0.f;
        o.w = (v[k].w != 0.f) ? (v[k].w - mean) * inv : 0.f;
        __stcs(&out[off + (size_t)k * NORM_THREADS], o);
    }
}

extern "C" void kernel_launch(void* const* d_in, const int* in_sizes, int n_in,
                              void* d_out, int out_size) {
    const float4* x   = (const float4*)d_in[0];
    float4*       out = (float4*)d_out;

    for (int g = 0; g < GROUPS; g++) {
        dim3 redGrid(RED_BLOCKS, BPG);
        reduce_finalize_kernel<<<redGrid, RED_THREADS>>>(x, g);

        dim3 normGrid(NORM_BLOCKS, BPG);
        normalize_kernel<<<normGrid, NORM_THREADS>>>(x, out, g);
    }
}

// round 4
// speedup vs baseline: 1.0713x; 1.0713x over previous
#include <cuda_runtime.h>
#include <cstdint>

#define EPS 1e-5f
#define NBATCH 16
#define GROUPS 2
#define BPG 8                            // 8 batches/group = 128MB ~ L2 capacity
#define PER (4 * 1024 * 1024)            // elements per batch (C*H*W)
#define PER4 (PER / 4)                   // float4s per batch = 1,048,576

#define RED_THREADS 256
#define RED_BLOCKS 256                   // blocks per batch -> 2048 blocks per group launch
#define RED_STRIDE (RED_BLOCKS * RED_THREADS)   // 65536
#define RED_ITERS (PER4 / RED_STRIDE)           // 16
#define RED_UNROLL 8

#define FIN_THREADS 256

#define NORM_THREADS 256
#define NORM_F4_PER_THREAD 4
#define NORM_F4_PER_BLOCK (NORM_THREADS * NORM_F4_PER_THREAD)   // 1024
#define NORM_BLOCKS (PER4 / NORM_F4_PER_BLOCK)                  // 1024 per batch

// Scratch (allocation-free requirement -> __device__ globals)
__device__ float        g_psum[NBATCH * RED_BLOCKS];
__device__ float        g_psumsq[NBATCH * RED_BLOCKS];
__device__ unsigned int g_pcnt[NBATCH * RED_BLOCKS];
__device__ float        g_mean[NBATCH];
__device__ float        g_inv[NBATCH];

// ---------------------------------------------------------------------------
// Pass 1 (per group): per-batch partial reduction of (sum, sumsq, nnz count).
// Masked entries are exactly 0.0f so sum/sumsq over ALL elements equal the
// masked sums -> branch-free hot loop. Unroll x8 with front-batched loads.
// ---------------------------------------------------------------------------
__global__ __launch_bounds__(RED_THREADS)
void reduce_kernel(const float4* __restrict__ x, int group) {
    const int b = group * BPG + blockIdx.y;
    const float4* xb = x + (size_t)b * PER4;

    float s = 0.f, ss = 0.f;
    unsigned int c = 0;

    const int base = blockIdx.x * RED_THREADS + threadIdx.x;

    #pragma unroll 1
    for (int j = 0; j < RED_ITERS; j += RED_UNROLL) {
        float4 v[RED_UNROLL];
        #pragma unroll
        for (int k = 0; k < RED_UNROLL; k++)
            v[k] = xb[base + (size_t)(j + k) * RED_STRIDE];
        #pragma unroll
        for (int k = 0; k < RED_UNROLL; k++) {
            s  += v[k].x + v[k].y + v[k].z + v[k].w;
            ss  = fmaf(v[k].x, v[k].x, ss);
            ss  = fmaf(v[k].y, v[k].y, ss);
            ss  = fmaf(v[k].z, v[k].z, ss);
            ss  = fmaf(v[k].w, v[k].w, ss);
            c  += (v[k].x != 0.f) + (v[k].y != 0.f) + (v[k].z != 0.f) + (v[k].w != 0.f);
        }
    }

    // block reduce
    #pragma unroll
    for (int off = 16; off > 0; off >>= 1) {
        s  += __shfl_xor_sync(0xFFFFFFFFu, s,  off);
        ss += __shfl_xor_sync(0xFFFFFFFFu, ss, off);
        c  += __shfl_xor_sync(0xFFFFFFFFu, c,  off);
    }

    __shared__ float sh_s[RED_THREADS / 32];
    __shared__ float sh_ss[RED_THREADS / 32];
    __shared__ unsigned int sh_c[RED_THREADS / 32];
    const int lane = threadIdx.x & 31;
    const int warp = threadIdx.x >> 5;
    if (lane == 0) { sh_s[warp] = s; sh_ss[warp] = ss; sh_c[warp] = c; }
    __syncthreads();

    if (warp == 0) {
        s  = (lane < RED_THREADS / 32) ? sh_s[lane]  : 0.f;
        ss = (lane < RED_THREADS / 32) ? sh_ss[lane] : 0.f;
        c  = (lane < RED_THREADS / 32) ? sh_c[lane]  : 0u;
        #pragma unroll
        for (int off = 4; off > 0; off >>= 1) {
            s  += __shfl_xor_sync(0xFFFFFFFFu, s,  off);
            ss += __shfl_xor_sync(0xFFFFFFFFu, ss, off);
            c  += __shfl_xor_sync(0xFFFFFFFFu, c,  off);
        }
        if (lane == 0) {
            const int idx = b * RED_BLOCKS + blockIdx.x;
            g_psum[idx]   = s;
            g_psumsq[idx] = ss;
            g_pcnt[idx]   = c;
        }
    }
}

// ---------------------------------------------------------------------------
// Pass 2 (per group): finalize, one block per batch. Double accumulation over
// the RED_BLOCKS partials.
// ---------------------------------------------------------------------------
__global__ __launch_bounds__(FIN_THREADS)
void finalize_kernel(int group) {
    const int b = group * BPG + blockIdx.x;
    const int t = threadIdx.x;

    double s  = (double)g_psum[b * RED_BLOCKS + t];
    double ss = (double)g_psumsq[b * RED_BLOCKS + t];
    unsigned long long c = g_pcnt[b * RED_BLOCKS + t];

    #pragma unroll
    for (int off = 16; off > 0; off >>= 1) {
        s  += __shfl_xor_sync(0xFFFFFFFFu, s,  off);
        ss += __shfl_xor_sync(0xFFFFFFFFu, ss, off);
        c  += __shfl_xor_sync(0xFFFFFFFFu, c,  off);
    }
    __shared__ double sh_s[FIN_THREADS / 32];
    __shared__ double sh_ss[FIN_THREADS / 32];
    __shared__ unsigned long long sh_c[FIN_THREADS / 32];
    const int lane = t & 31, warp = t >> 5;
    if (lane == 0) { sh_s[warp] = s; sh_ss[warp] = ss; sh_c[warp] = c; }
    __syncthreads();
    if (t == 0) {
        double S = 0.0, SS = 0.0; unsigned long long C = 0;
        #pragma unroll
        for (int w = 0; w < FIN_THREADS / 32; w++) { S += sh_s[w]; SS += sh_ss[w]; C += sh_c[w]; }
        const double n    = (double)C;
        const double mean = S / n;
        const double var  = (SS - S * S / n) / (n - 1.0);   // m2 term analytically 0
        g_mean[b] = (float)mean;
        g_inv[b]  = (float)(1.0 / (sqrt(var) + (double)EPS));
    }
}

// ---------------------------------------------------------------------------
// Pass 3 (per group): elementwise normalize. x for this group is mostly
// L2-resident from the reduce pass; __stcs streaming stores keep the output
// from evicting it. Ascending order so the (few) cold low addresses miss first.
// ---------------------------------------------------------------------------
__global__ __launch_bounds__(NORM_THREADS)
void normalize_kernel(const float4* __restrict__ x, float4* __restrict__ out, int group) {
    const int b = group * BPG + blockIdx.y;
    const size_t off = (size_t)b * PER4 + (size_t)blockIdx.x * NORM_F4_PER_BLOCK + threadIdx.x;

    const float mean = g_mean[b];
    const float inv  = g_inv[b];

    float4 v[NORM_F4_PER_THREAD];
    #pragma unroll
    for (int k = 0; k < NORM_F4_PER_THREAD; k++)
        v[k] = x[off + (size_t)k * NORM_THREADS];

    #pragma unroll
    for (int k = 0; k < NORM_F4_PER_THREAD; k++) {
        float4 o;
        o.x = (v[k].x != 0.f) ? (v[k].x - mean) * inv : 0.f;
        o.y = (v[k].y != 0.f) ? (v[k].y - mean) * inv : 0.f;
        o.z = (v[k].z != 0.f) ? (v[k].z - mean) * inv : 0.f;
        o.w = (v[k].w != 0.f) ? (v[k].w - mean) * inv : 0.f;
        __stcs(&out[off + (size_t)k * NORM_THREADS], o);
    }
}

extern "C" void kernel_launch(void* const* d_in, const int* in_sizes, int n_in,
                              void* d_out, int out_size) {
    const float4* x   = (const float4*)d_in[0];
    float4*       out = (float4*)d_out;

    for (int g = 0; g < GROUPS; g++) {
        dim3 redGrid(RED_BLOCKS, BPG);
        reduce_kernel<<<redGrid, RED_THREADS>>>(x, g);

        finalize_kernel<<<BPG, FIN_THREADS>>>(g);

        dim3 normGrid(NORM_BLOCKS, BPG);
        normalize_kernel<<<normGrid, NORM_THREADS>>>(x, out, g);
    }
}